// round 2
// baseline (speedup 1.0000x reference)
#include <cuda_runtime.h>
#include <math.h>

#define BB 8
#define NN 512
#define FF 64
#define EE 16
#define HH 4
#define HD 16
#define NPOS (BB*NN*NN)    // 2097152
#define ROWS (BB*NN)       // 4096

// ---------------- scratch (static device globals; no runtime alloc) ----------
__device__ float g_h  [ROWS*FF];
__device__ float g_sr [ROWS*HH];
__device__ float g_sc [ROWS*HH];
__device__ float g_se [NPOS];          // 8 MB
__device__ float g_msg[ROWS*FF];

// ---------------- packed f32x2 helpers ---------------------------------------
union f2u { float2 f; unsigned long long u; };

__device__ __forceinline__ float2 ffma2(float2 a, float2 b, float2 c) {
    f2u A, Bv, C, D; A.f = a; Bv.f = b; C.f = c;
    asm("fma.rn.f32x2 %0, %1, %2, %3;" : "=l"(D.u) : "l"(A.u), "l"(Bv.u), "l"(C.u));
    return D.f;
}
__device__ __forceinline__ float2 fadd2(float2 a, float2 b) {
    f2u A, Bv, D; A.f = a; Bv.f = b;
    asm("add.rn.f32x2 %0, %1, %2;" : "=l"(D.u) : "l"(A.u), "l"(Bv.u));
    return D.f;
}
__device__ __forceinline__ float2 fmul2(float2 a, float2 b) {
    f2u A, Bv, D; A.f = a; Bv.f = b;
    asm("mul.rn.f32x2 %0, %1, %2;" : "=l"(D.u) : "l"(A.u), "l"(Bv.u));
    return D.f;
}

// ---------------- K1: node LN -> Wn GEMM -> sr/sc -----------------------------
__global__ void k_node(const float* __restrict__ node, const float* __restrict__ g1,
                       const float* __restrict__ b1, const float* __restrict__ Wn,
                       const float* __restrict__ bn, const float* __restrict__ A) {
    int row = blockIdx.x;
    int f = threadIdx.x;               // 64 threads
    __shared__ float lns[FF], hs[FF], redm[2], redv[2];
    __shared__ float a_row[HD], a_col[HD];

    if (f < HD) {
        float s = 0.f;
        #pragma unroll
        for (int h = 0; h < HH; h++) s += A[h*48 + f];
        a_row[f] = s;
    } else if (f < 2*HD) {
        int x = f - HD;
        float s = 0.f;
        #pragma unroll
        for (int h = 0; h < HH; h++) s += A[h*48 + HD + x];
        a_col[x] = s;
    }

    float x = node[row*FF + f];
    float v = x;
    #pragma unroll
    for (int o = 16; o; o >>= 1) v += __shfl_xor_sync(0xffffffffu, v, o);
    if ((f & 31) == 0) redm[f >> 5] = v;
    __syncthreads();
    float mu = (redm[0] + redm[1]) * (1.f/FF);
    float d = x - mu;
    v = d * d;
    #pragma unroll
    for (int o = 16; o; o >>= 1) v += __shfl_xor_sync(0xffffffffu, v, o);
    if ((f & 31) == 0) redv[f >> 5] = v;
    __syncthreads();
    float var = (redv[0] + redv[1]) * (1.f/FF);
    lns[f] = d * rsqrtf(var + 1e-5f) * g1[f] + b1[f];
    __syncthreads();

    float acc = bn[f];
    const float* wr = Wn + f*FF;
    #pragma unroll 16
    for (int k = 0; k < FF; k++) acc += lns[k] * wr[k];
    g_h[row*FF + f] = acc;
    hs[f] = acc;
    __syncthreads();

    if (f < HH) {
        float s = 0.f;
        #pragma unroll
        for (int x2 = 0; x2 < HD; x2++) s += hs[f*HD + x2] * a_row[x2];
        g_sr[row*HH + f] = s;
    } else if (f < 2*HH) {
        int hh = f - HH;
        float s = 0.f;
        #pragma unroll
        for (int x2 = 0; x2 < HD; x2++) s += hs[hh*HD + x2] * a_col[x2];
        g_sc[row*HH + hh] = s;
    }
}

// ---------------- K2: edge LN -> MLP -> residual -> LN -> e + se --------------
__global__ __launch_bounds__(128) void k_edge(
    const float* __restrict__ edge,
    const float* __restrict__ g2, const float* __restrict__ b2,
    const float* __restrict__ We1, const float* __restrict__ be1,
    const float* __restrict__ We2, const float* __restrict__ be2,
    const float* __restrict__ lg, const float* __restrict__ lb,
    const float* __restrict__ A, float* __restrict__ e_out) {

    __shared__ float2 W1s[32*16], W2s[16*32];
    __shared__ float2 ln2g[EE], ln2b[EE], lneg[EE], lneb[EE], be1s[32], be2s[EE], aes[EE];

    int tid = threadIdx.x;
    for (int i = tid; i < 512; i += 128) {
        float w = We1[i]; W1s[i] = make_float2(w, w);
        float w2 = We2[i]; W2s[i] = make_float2(w2, w2);
    }
    if (tid < EE) {
        ln2g[tid] = make_float2(g2[tid], g2[tid]);
        ln2b[tid] = make_float2(b2[tid], b2[tid]);
        lneg[tid] = make_float2(lg[tid], lg[tid]);
        lneb[tid] = make_float2(lb[tid], lb[tid]);
        be2s[tid] = make_float2(be2[tid], be2[tid]);
        float s = 0.f;
        #pragma unroll
        for (int h = 0; h < HH; h++) s += A[h*48 + 2*HD + tid];
        aes[tid] = make_float2(s, s);
    }
    if (tid < 32) be1s[tid] = make_float2(be1[tid], be1[tid]);
    __syncthreads();

    size_t pair = (size_t)blockIdx.x * 128 + tid;     // 2 positions per thread
    const float4* ep = (const float4*)edge + pair * 8;

    const float2 zero2 = make_float2(0.f, 0.f);
    const float2 neg1  = make_float2(-1.f, -1.f);
    const float2 inv16 = make_float2(1.f/16.f, 1.f/16.f);

    float2 X[EE];
    {
        float4 v0[4], v1[4];
        #pragma unroll
        for (int i = 0; i < 4; i++) { v0[i] = ep[i]; v1[i] = ep[4+i]; }
        const float* p0 = (const float*)v0;
        const float* p1 = (const float*)v1;
        #pragma unroll
        for (int k = 0; k < EE; k++) X[k] = make_float2(p0[k], p1[k]);
    }

    // LN over E=16
    float2 s = zero2;
    #pragma unroll
    for (int k = 0; k < EE; k++) s = fadd2(s, X[k]);
    float2 mu = fmul2(s, inv16);
    float2 q = zero2;
    #pragma unroll
    for (int k = 0; k < EE; k++) { float2 d = ffma2(mu, neg1, X[k]); q = ffma2(d, d, q); }
    float2 var = fmul2(q, inv16);
    float2 rs = make_float2(rsqrtf(var.x + 1e-5f), rsqrtf(var.y + 1e-5f));
    #pragma unroll
    for (int k = 0; k < EE; k++) {
        float2 d = ffma2(mu, neg1, X[k]);
        X[k] = ffma2(d, fmul2(rs, ln2g[k]), ln2b[k]);
    }

    // GEMM1 (16->32) + celu
    float2 Hc[32];
    #pragma unroll 4
    for (int o = 0; o < 32; o++) {
        float2 acc = be1s[o];
        #pragma unroll
        for (int k = 0; k < 16; k++) acc = ffma2(X[k], W1s[o*16 + k], acc);
        float t0 = __expf(fminf(acc.x, 0.f)) - 1.f;
        float t1 = __expf(fminf(acc.y, 0.f)) - 1.f;
        Hc[o] = make_float2(fmaxf(acc.x, 0.f) + t0, fmaxf(acc.y, 0.f) + t1);
    }

    // GEMM2 (32->16)
    float2 Y[EE];
    #pragma unroll 4
    for (int o = 0; o < 16; o++) {
        float2 acc = be2s[o];
        #pragma unroll
        for (int k = 0; k < 32; k++) acc = ffma2(Hc[k], W2s[o*32 + k], acc);
        Y[o] = acc;
    }

    // residual (reload original edge; L1-hot)
    {
        float4 v0[4], v1[4];
        #pragma unroll
        for (int i = 0; i < 4; i++) { v0[i] = ep[i]; v1[i] = ep[4+i]; }
        const float* p0 = (const float*)v0;
        const float* p1 = (const float*)v1;
        #pragma unroll
        for (int k = 0; k < EE; k++) Y[k] = fadd2(Y[k], make_float2(p0[k], p1[k]));
    }

    // final LN + se
    s = zero2;
    #pragma unroll
    for (int k = 0; k < EE; k++) s = fadd2(s, Y[k]);
    mu = fmul2(s, inv16);
    q = zero2;
    #pragma unroll
    for (int k = 0; k < EE; k++) { float2 d = ffma2(mu, neg1, Y[k]); q = ffma2(d, d, q); }
    var = fmul2(q, inv16);
    rs = make_float2(rsqrtf(var.x + 1e-5f), rsqrtf(var.y + 1e-5f));

    float2 se_acc = zero2;
    #pragma unroll
    for (int k = 0; k < EE; k++) {
        float2 d = ffma2(mu, neg1, Y[k]);
        float2 yv = ffma2(d, fmul2(rs, lneg[k]), lneb[k]);
        Y[k] = yv;
        se_acc = ffma2(yv, aes[k], se_acc);
    }

    float4* eo = (float4*)e_out + pair * 8;
    #pragma unroll
    for (int i = 0; i < 4; i++)
        eo[i]   = make_float4(Y[i*4+0].x, Y[i*4+1].x, Y[i*4+2].x, Y[i*4+3].x);
    #pragma unroll
    for (int i = 0; i < 4; i++)
        eo[4+i] = make_float4(Y[i*4+0].y, Y[i*4+1].y, Y[i*4+2].y, Y[i*4+3].y);

    g_se[pair*2]     = se_acc.x;
    g_se[pair*2 + 1] = se_acc.y;
}

// ---------------- K3: masked leaky softmax + message aggregation --------------
__global__ __launch_bounds__(128) void k_attn(const int* __restrict__ adj) {
    __shared__ float hs[128*64];   // 32 KB j-tile of h
    __shared__ float scs[128*4];   // 2 KB

    int tid = threadIdx.x;
    int il = tid >> 2, hh = tid & 3;
    int b = blockIdx.y;
    int ig = blockIdx.x * 32 + il;
    int rowi = b*NN + ig;

    float sr_v = g_sr[rowi*HH + hh];
    float m = -3.4e38f, ssum = 0.f;
    float acc[16];
    #pragma unroll
    for (int x = 0; x < 16; x++) acc[x] = 0.f;

    const float* sep = g_se + (size_t)rowi * NN;
    const int*   ap  = adj  + (size_t)rowi * NN;

    for (int jt = 0; jt < 4; jt++) {
        int j0 = jt * 128;
        const float4* hsrc = (const float4*)(g_h + (size_t)(b*NN + j0) * FF);
        float4* hdst = (float4*)hs;
        for (int i = tid; i < 128*16; i += 128) hdst[i] = hsrc[i];
        {
            const float4* ssrc = (const float4*)(g_sc + (size_t)(b*NN + j0) * HH);
            ((float4*)scs)[tid] = ssrc[tid];
        }
        __syncthreads();

        for (int jl = 0; jl < 128; jl++) {
            int j = j0 + jl;
            float lgt = sr_v + scs[jl*4 + hh] + sep[j];
            if (ap[j] == 0) lgt = -1e9f;
            lgt = lgt > 0.f ? lgt : 0.2f * lgt;
            lgt = fminf(fmaxf(lgt, -1e9f), 1e9f);
            float w;
            if (lgt > m) {
                float c = __expf(m - lgt);
                ssum *= c;
                #pragma unroll
                for (int x = 0; x < 16; x++) acc[x] *= c;
                m = lgt;
                w = 1.f;
            } else {
                w = __expf(lgt - m);
            }
            ssum += w;
            const float4* hp = (const float4*)(hs + jl*64 + hh*16);
            #pragma unroll
            for (int x4 = 0; x4 < 4; x4++) {
                float4 hv = hp[x4];
                acc[x4*4+0] += w * hv.x;
                acc[x4*4+1] += w * hv.y;
                acc[x4*4+2] += w * hv.z;
                acc[x4*4+3] += w * hv.w;
            }
        }
        __syncthreads();
    }

    float inv = 1.f / ssum;
    float* mo = g_msg + (size_t)rowi * FF + hh*16;
    #pragma unroll
    for (int x = 0; x < 16; x++) mo[x] = acc[x] * inv;
}

// ---------------- K4: out projection + residual + leaky + LN ------------------
__global__ void k_out(const float* __restrict__ node, const float* __restrict__ Wo,
                      const float* __restrict__ bo, const float* __restrict__ lg,
                      const float* __restrict__ lb, float* __restrict__ outp) {
    int row = blockIdx.x;
    int f = threadIdx.x;            // 64 threads
    __shared__ float ms[FF], redm[2], redv[2];
    ms[f] = g_msg[row*FF + f];
    __syncthreads();

    float acc = bo[f] + node[row*FF + f];
    const float* wr = Wo + f*FF;
    #pragma unroll 16
    for (int k = 0; k < FF; k++) acc += ms[k] * wr[k];
    acc = acc > 0.f ? acc : 0.2f * acc;

    float v = acc;
    #pragma unroll
    for (int o = 16; o; o >>= 1) v += __shfl_xor_sync(0xffffffffu, v, o);
    if ((f & 31) == 0) redm[f >> 5] = v;
    __syncthreads();
    float mu = (redm[0] + redm[1]) * (1.f/FF);
    float d = acc - mu;
    v = d * d;
    #pragma unroll
    for (int o = 16; o; o >>= 1) v += __shfl_xor_sync(0xffffffffu, v, o);
    if ((f & 31) == 0) redv[f >> 5] = v;
    __syncthreads();
    float var = (redv[0] + redv[1]) * (1.f/FF);
    outp[row*FF + f] = d * rsqrtf(var + 1e-5f) * lg[f] + lb[f];
}

// ---------------- K5: adj -> float copy ---------------------------------------
__global__ void k_adj(const int* __restrict__ adj, float* __restrict__ oadj) {
    int i = blockIdx.x * 256 + threadIdx.x;
    const int4* s = (const int4*)adj;
    float4* d = (float4*)oadj;
    int4 v = s[i];
    d[i] = make_float4((float)v.x, (float)v.y, (float)v.z, (float)v.w);
}

// ---------------- launch -------------------------------------------------------
extern "C" void kernel_launch(void* const* d_in, const int* in_sizes, int n_in,
                              void* d_out, int out_size) {
    const float* node  = (const float*)d_in[0];
    const float* edge  = (const float*)d_in[1];
    const int*   adj   = (const int*)  d_in[2];
    const float* ln1_g = (const float*)d_in[3];
    const float* ln1_b = (const float*)d_in[4];
    const float* Wn    = (const float*)d_in[5];
    const float* bn    = (const float*)d_in[6];
    const float* ln2_g = (const float*)d_in[7];
    const float* ln2_b = (const float*)d_in[8];
    const float* We1   = (const float*)d_in[9];
    const float* be1   = (const float*)d_in[10];
    const float* We2   = (const float*)d_in[11];
    const float* be2   = (const float*)d_in[12];
    const float* lne_g = (const float*)d_in[13];
    const float* lne_b = (const float*)d_in[14];
    const float* attnA = (const float*)d_in[15];
    const float* Wo    = (const float*)d_in[16];
    const float* bo    = (const float*)d_in[17];
    const float* lno_g = (const float*)d_in[18];
    const float* lno_b = (const float*)d_in[19];

    float* out     = (float*)d_out;                       // (B,N,F)
    float* e_out   = out + (size_t)ROWS * FF;             // (B,N,N,E)
    float* adj_out = e_out + (size_t)NPOS * EE;           // (B,N,N)

    k_node<<<ROWS, 64>>>(node, ln1_g, ln1_b, Wn, bn, attnA);
    k_edge<<<NPOS/256, 128>>>(edge, ln2_g, ln2_b, We1, be1, We2, be2,
                              lne_g, lne_b, attnA, e_out);
    k_attn<<<dim3(NN/32, BB), 128>>>(adj);
    k_out<<<ROWS, 64>>>(node, Wo, bo, lno_g, lno_b, out);
    k_adj<<<NPOS/1024, 256>>>(adj, adj_out);
}

// round 3
// speedup vs baseline: 1.7968x; 1.7968x over previous
#include <cuda_runtime.h>
#include <math.h>

#define BB 8
#define NN 512
#define FF 64
#define EE 16
#define HH 4
#define HD 16
#define NPOS (BB*NN*NN)    // 2097152
#define ROWS (BB*NN)       // 4096

// ---------------- scratch ------------------------------------------------------
__device__ float g_h  [ROWS*FF];
__device__ float g_sr [ROWS*HH];
__device__ float g_sc [ROWS*HH];
__device__ float g_se [NPOS];
__device__ float g_msg[ROWS*FF];

// ---------------- packed f32x2 helpers ----------------------------------------
union f2u { float2 f; unsigned long long u; };

__device__ __forceinline__ float2 ffma2(float2 a, float2 b, float2 c) {
    f2u A, Bv, C, D; A.f = a; Bv.f = b; C.f = c;
    asm("fma.rn.f32x2 %0, %1, %2, %3;" : "=l"(D.u) : "l"(A.u), "l"(Bv.u), "l"(C.u));
    return D.f;
}
__device__ __forceinline__ float2 fadd2(float2 a, float2 b) {
    f2u A, Bv, D; A.f = a; Bv.f = b;
    asm("add.rn.f32x2 %0, %1, %2;" : "=l"(D.u) : "l"(A.u), "l"(Bv.u));
    return D.f;
}
__device__ __forceinline__ float2 fmul2(float2 a, float2 b) {
    f2u A, Bv, D; A.f = a; Bv.f = b;
    asm("mul.rn.f32x2 %0, %1, %2;" : "=l"(D.u) : "l"(A.u), "l"(Bv.u));
    return D.f;
}

// ---------------- K1: node LN -> Wn GEMM -> sr/sc (64 rows / block) ------------
__global__ __launch_bounds__(256) void k_node(
        const float* __restrict__ node, const float* __restrict__ g1,
        const float* __restrict__ b1, const float* __restrict__ Wn,
        const float* __restrict__ bn, const float* __restrict__ A) {
    __shared__ __align__(16) float ns[64*68];    // node tile -> normalized in place
    __shared__ float Wns[64*65];                 // Wn[f][k], pad 65 (scalar reads)
    __shared__ __align__(16) float hs[64*68];    // h results
    __shared__ float arow[HD], acol[HD];

    int tid = threadIdx.x;
    int row0 = blockIdx.x * 64;

    if (tid < HD) {
        float s = 0.f;
        #pragma unroll
        for (int h = 0; h < HH; h++) s += A[h*48 + tid];
        arow[tid] = s;
    } else if (tid < 2*HD) {
        int x = tid - HD; float s = 0.f;
        #pragma unroll
        for (int h = 0; h < HH; h++) s += A[h*48 + HD + x];
        acol[x] = s;
    }

    // stage node tile (coalesced float4)
    {
        const float4* src = (const float4*)(node + (size_t)row0 * FF);
        #pragma unroll
        for (int i = tid; i < 64*16; i += 256) {
            int r = i >> 4, c4 = i & 15;
            *(float4*)&ns[r*68 + c4*4] = src[i];
        }
    }
    // stage Wn (scalar, conflict-free)
    #pragma unroll
    for (int i = tid; i < 64*64; i += 256) {
        int f = i >> 6, k = i & 63;
        Wns[f*65 + k] = Wn[i];
    }
    __syncthreads();

    // LN per row: 4 threads per row
    {
        int r = tid >> 2, sub = tid & 3;
        float s = 0.f;
        #pragma unroll
        for (int t = 0; t < 16; t++) s += ns[r*68 + sub + 4*t];
        s += __shfl_xor_sync(0xffffffffu, s, 1);
        s += __shfl_xor_sync(0xffffffffu, s, 2);
        float mu = s * (1.f/FF);
        float q = 0.f;
        #pragma unroll
        for (int t = 0; t < 16; t++) { float d = ns[r*68 + sub + 4*t] - mu; q += d*d; }
        q += __shfl_xor_sync(0xffffffffu, q, 1);
        q += __shfl_xor_sync(0xffffffffu, q, 2);
        float rs = rsqrtf(q * (1.f/FF) + 1e-5f);
        #pragma unroll
        for (int t = 0; t < 16; t++) {
            int k = sub + 4*t;
            ns[r*68 + k] = (ns[r*68 + k] - mu) * rs * g1[k] + b1[k];
        }
    }
    __syncthreads();

    // GEMM: thread = (col f, rowgroup rg of 16 rows)
    {
        int f  = tid & 63;
        int rg = tid >> 6;        // 0..3
        float acc[16];
        float bv = bn[f];
        #pragma unroll
        for (int t = 0; t < 16; t++) acc[t] = bv;
        #pragma unroll 8
        for (int k = 0; k < 64; k++) {
            float wv = Wns[f*65 + k];
            #pragma unroll
            for (int t = 0; t < 16; t++)
                acc[t] = fmaf(ns[(rg*16 + t)*68 + k], wv, acc[t]);
        }
        #pragma unroll
        for (int t = 0; t < 16; t++) {
            int r = rg*16 + t;
            g_h[(size_t)(row0 + r)*FF + f] = acc[t];
            hs[r*68 + f] = acc[t];
        }
    }
    __syncthreads();

    // sr/sc: thread = (row, head)
    {
        int r = tid >> 2, hh = tid & 3;
        float sr = 0.f, sc = 0.f;
        #pragma unroll
        for (int x = 0; x < HD; x++) {
            float hv = hs[r*68 + hh*HD + x];
            sr = fmaf(hv, arow[x], sr);
            sc = fmaf(hv, acol[x], sc);
        }
        g_sr[(size_t)(row0 + r)*HH + hh] = sr;
        g_sc[(size_t)(row0 + r)*HH + hh] = sc;
    }
}

// ---------------- K2: edge LN -> fused MLP -> residual -> LN -> e + se ---------
__global__ __launch_bounds__(128) void k_edge(
    const float* __restrict__ edge,
    const float* __restrict__ g2, const float* __restrict__ b2,
    const float* __restrict__ We1, const float* __restrict__ be1,
    const float* __restrict__ We2, const float* __restrict__ be2,
    const float* __restrict__ lg, const float* __restrict__ lb,
    const float* __restrict__ A, float* __restrict__ e_out) {

    __shared__ float2 W1s[32*16], W2s[16*32];
    __shared__ float2 ln2g[EE], ln2b[EE], lneg[EE], lneb[EE], be1s[32], be2s[EE], aes[EE];
    __shared__ float est[256*17];    // staged edge rows, pad 17

    int tid = threadIdx.x;
    for (int i = tid; i < 512; i += 128) {
        float w = We1[i]; W1s[i] = make_float2(w, w);
        float w2 = We2[i]; W2s[i] = make_float2(w2, w2);
    }
    if (tid < EE) {
        ln2g[tid] = make_float2(g2[tid], g2[tid]);
        ln2b[tid] = make_float2(b2[tid], b2[tid]);
        lneg[tid] = make_float2(lg[tid], lg[tid]);
        lneb[tid] = make_float2(lb[tid], lb[tid]);
        be2s[tid] = make_float2(be2[tid], be2[tid]);
        float s = 0.f;
        #pragma unroll
        for (int h = 0; h < HH; h++) s += A[h*48 + 2*HD + tid];
        aes[tid] = make_float2(s, s);
    }
    if (tid < 32) be1s[tid] = make_float2(be1[tid], be1[tid]);

    // stage 256 positions (coalesced)
    size_t pos_base = (size_t)blockIdx.x * 256;
    {
        const float4* src = (const float4*)edge + pos_base*4;
        #pragma unroll
        for (int i = tid; i < 1024; i += 128) {
            float4 v = src[i];
            int p = i >> 2, c4 = i & 3;
            float* d = &est[p*17 + c4*4];
            d[0] = v.x; d[1] = v.y; d[2] = v.z; d[3] = v.w;
        }
    }
    __syncthreads();

    int p0 = tid, p1 = tid + 128;
    const float2 zero2 = make_float2(0.f, 0.f);
    const float2 neg1  = make_float2(-1.f, -1.f);
    const float2 inv16 = make_float2(1.f/16.f, 1.f/16.f);

    float2 X[EE];
    #pragma unroll
    for (int k = 0; k < EE; k++) X[k] = make_float2(est[p0*17 + k], est[p1*17 + k]);

    // LN over E
    float2 s = zero2;
    #pragma unroll
    for (int k = 0; k < EE; k++) s = fadd2(s, X[k]);
    float2 mu = fmul2(s, inv16);
    float2 q = zero2;
    #pragma unroll
    for (int k = 0; k < EE; k++) { float2 d = ffma2(mu, neg1, X[k]); q = ffma2(d, d, q); }
    float2 var = fmul2(q, inv16);
    float2 rs = make_float2(rsqrtf(var.x + 1e-5f), rsqrtf(var.y + 1e-5f));
    #pragma unroll
    for (int k = 0; k < EE; k++) {
        float2 d = ffma2(mu, neg1, X[k]);
        X[k] = ffma2(d, fmul2(rs, ln2g[k]), ln2b[k]);
    }

    // fused GEMM1 -> celu -> GEMM2  (no Hc array)
    float2 Y[EE];
    #pragma unroll
    for (int o = 0; o < EE; o++) Y[o] = be2s[o];
    #pragma unroll 2
    for (int kk = 0; kk < 32; kk++) {
        float2 a = be1s[kk];
        #pragma unroll
        for (int k = 0; k < 16; k++) a = ffma2(X[k], W1s[kk*16 + k], a);
        float t0 = __expf(fminf(a.x, 0.f)) - 1.f;
        float t1 = __expf(fminf(a.y, 0.f)) - 1.f;
        float2 hc = make_float2(fmaxf(a.x, 0.f) + t0, fmaxf(a.y, 0.f) + t1);
        #pragma unroll
        for (int o = 0; o < 16; o++) Y[o] = ffma2(hc, W2s[o*32 + kk], Y[o]);
    }

    // residual from staged original
    #pragma unroll
    for (int k = 0; k < EE; k++)
        Y[k] = fadd2(Y[k], make_float2(est[p0*17 + k], est[p1*17 + k]));

    // final LN + se
    s = zero2;
    #pragma unroll
    for (int k = 0; k < EE; k++) s = fadd2(s, Y[k]);
    mu = fmul2(s, inv16);
    q = zero2;
    #pragma unroll
    for (int k = 0; k < EE; k++) { float2 d = ffma2(mu, neg1, Y[k]); q = ffma2(d, d, q); }
    var = fmul2(q, inv16);
    rs = make_float2(rsqrtf(var.x + 1e-5f), rsqrtf(var.y + 1e-5f));

    float2 se_acc = zero2;
    #pragma unroll
    for (int k = 0; k < EE; k++) {
        float2 d = ffma2(mu, neg1, Y[k]);
        float2 yv = ffma2(d, fmul2(rs, lneg[k]), lneb[k]);
        Y[k] = yv;
        se_acc = ffma2(yv, aes[k], se_acc);
    }

    // stage results (each thread owns rows p0,p1 -> no sync needed before write)
    #pragma unroll
    for (int k = 0; k < EE; k++) { est[p0*17 + k] = Y[k].x; est[p1*17 + k] = Y[k].y; }
    g_se[pos_base + p0] = se_acc.x;
    g_se[pos_base + p1] = se_acc.y;
    __syncthreads();

    // coalesced store
    {
        float4* dst = (float4*)e_out + pos_base*4;
        #pragma unroll
        for (int i = tid; i < 1024; i += 128) {
            int p = i >> 2, c4 = i & 3;
            const float* sp = &est[p*17 + c4*4];
            dst[i] = make_float4(sp[0], sp[1], sp[2], sp[3]);
        }
    }
}

// ---------------- K3: two-pass masked leaky softmax + aggregation --------------
// thread = (i_local, head, x-quarter): 16 * 4 * 4 = 256 threads; block = 16 rows i
__global__ __launch_bounds__(256) void k_attn(const int* __restrict__ adj) {
    __shared__ __align__(16) float hsm[128*64];  // j-tile of h (32 KB)
    __shared__ float scs[128*4];

    int tid = threadIdx.x;
    int sub = tid & 3;
    int hh  = (tid >> 2) & 3;
    int il  = tid >> 4;
    int b = blockIdx.y;
    int ig = blockIdx.x * 16 + il;
    int rowi = b*NN + ig;

    const float* sep = g_se + (size_t)rowi * NN;
    const int*   ap  = adj  + (size_t)rowi * NN;
    float sr_v = g_sr[rowi*HH + hh];
    const float* scg = g_sc + (size_t)b*NN*HH;

    // pass 1: max over j (split across 4 subs, combine via shfl)
    float m = -3.4e38f;
    #pragma unroll 4
    for (int t = 0; t < 128; t++) {
        int j = sub + 4*t;
        float lgt = sr_v + scg[j*HH + hh] + sep[j];
        if (ap[j] == 0) lgt = -1e9f;
        lgt = lgt > 0.f ? lgt : 0.2f*lgt;
        lgt = fminf(fmaxf(lgt, -1e9f), 1e9f);
        m = fmaxf(m, lgt);
    }
    m = fmaxf(m, __shfl_xor_sync(0xffffffffu, m, 1));
    m = fmaxf(m, __shfl_xor_sync(0xffffffffu, m, 2));

    // pass 2: weights + aggregation
    float ssum = 0.f;
    float a0 = 0.f, a1 = 0.f, a2 = 0.f, a3 = 0.f;
    for (int jt = 0; jt < 4; jt++) {
        int j0 = jt * 128;
        __syncthreads();
        {
            const float4* hsrc = (const float4*)(g_h + (size_t)(b*NN + j0) * FF);
            #pragma unroll
            for (int i = tid; i < 128*16; i += 256) ((float4*)hsm)[i] = hsrc[i];
            if (tid < 128)
                ((float4*)scs)[tid] = ((const float4*)(scg + (size_t)j0*HH))[tid];
        }
        __syncthreads();
        #pragma unroll 2
        for (int jl = 0; jl < 128; jl++) {
            int j = j0 + jl;
            float lgt = sr_v + scs[jl*4 + hh] + sep[j];
            if (ap[j] == 0) lgt = -1e9f;
            lgt = lgt > 0.f ? lgt : 0.2f*lgt;
            lgt = fminf(fmaxf(lgt, -1e9f), 1e9f);
            float w = __expf(lgt - m);
            ssum += w;
            float4 hv = *(const float4*)(hsm + jl*64 + hh*16 + sub*4);
            a0 = fmaf(w, hv.x, a0);
            a1 = fmaf(w, hv.y, a1);
            a2 = fmaf(w, hv.z, a2);
            a3 = fmaf(w, hv.w, a3);
        }
    }
    float inv = 1.f / ssum;
    *(float4*)(g_msg + (size_t)rowi*FF + hh*16 + sub*4) =
        make_float4(a0*inv, a1*inv, a2*inv, a3*inv);
}

// ---------------- K4: out proj + residual + leaky + LN (64 rows / block) -------
__global__ __launch_bounds__(256) void k_out(
        const float* __restrict__ node, const float* __restrict__ Wo,
        const float* __restrict__ bo, const float* __restrict__ lg,
        const float* __restrict__ lb, float* __restrict__ outp) {
    __shared__ __align__(16) float ms[64*68];
    __shared__ float Wos[64*65];
    __shared__ float hsr[64*68];

    int tid = threadIdx.x;
    int row0 = blockIdx.x * 64;

    {
        const float4* src = (const float4*)(g_msg + (size_t)row0 * FF);
        #pragma unroll
        for (int i = tid; i < 64*16; i += 256) {
            int r = i >> 4, c4 = i & 15;
            *(float4*)&ms[r*68 + c4*4] = src[i];
        }
    }
    #pragma unroll
    for (int i = tid; i < 64*64; i += 256) {
        int f = i >> 6, k = i & 63;
        Wos[f*65 + k] = Wo[i];
    }
    __syncthreads();

    {
        int f  = tid & 63;
        int rg = tid >> 6;
        float acc[16];
        float bv = bo[f];
        #pragma unroll
        for (int t = 0; t < 16; t++) acc[t] = bv;
        #pragma unroll 8
        for (int k = 0; k < 64; k++) {
            float wv = Wos[f*65 + k];
            #pragma unroll
            for (int t = 0; t < 16; t++)
                acc[t] = fmaf(ms[(rg*16 + t)*68 + k], wv, acc[t]);
        }
        #pragma unroll
        for (int t = 0; t < 16; t++) {
            int r = rg*16 + t;
            float v = acc[t] + node[(size_t)(row0 + r)*FF + f];
            v = v > 0.f ? v : 0.2f*v;
            hsr[r*68 + f] = v;
        }
    }
    __syncthreads();

    // LN per row: 4 threads/row
    {
        int r = tid >> 2, sub = tid & 3;
        float s = 0.f;
        #pragma unroll
        for (int t = 0; t < 16; t++) s += hsr[r*68 + sub + 4*t];
        s += __shfl_xor_sync(0xffffffffu, s, 1);
        s += __shfl_xor_sync(0xffffffffu, s, 2);
        float mu = s * (1.f/FF);
        float q = 0.f;
        #pragma unroll
        for (int t = 0; t < 16; t++) { float d = hsr[r*68 + sub + 4*t] - mu; q += d*d; }
        q += __shfl_xor_sync(0xffffffffu, q, 1);
        q += __shfl_xor_sync(0xffffffffu, q, 2);
        float rsv = rsqrtf(q * (1.f/FF) + 1e-5f);
        #pragma unroll
        for (int t = 0; t < 16; t++) {
            int k = sub + 4*t;
            outp[(size_t)(row0 + r)*FF + k] = (hsr[r*68 + k] - mu) * rsv * lg[k] + lb[k];
        }
    }
}

// ---------------- K5: adj -> float copy ---------------------------------------
__global__ void k_adj(const int* __restrict__ adj, float* __restrict__ oadj) {
    int i = blockIdx.x * 256 + threadIdx.x;
    const int4* s = (const int4*)adj;
    float4* d = (float4*)oadj;
    int4 v = s[i];
    d[i] = make_float4((float)v.x, (float)v.y, (float)v.z, (float)v.w);
}

// ---------------- launch -------------------------------------------------------
extern "C" void kernel_launch(void* const* d_in, const int* in_sizes, int n_in,
                              void* d_out, int out_size) {
    const float* node  = (const float*)d_in[0];
    const float* edge  = (const float*)d_in[1];
    const int*   adj   = (const int*)  d_in[2];
    const float* ln1_g = (const float*)d_in[3];
    const float* ln1_b = (const float*)d_in[4];
    const float* Wn    = (const float*)d_in[5];
    const float* bn    = (const float*)d_in[6];
    const float* ln2_g = (const float*)d_in[7];
    const float* ln2_b = (const float*)d_in[8];
    const float* We1   = (const float*)d_in[9];
    const float* be1   = (const float*)d_in[10];
    const float* We2   = (const float*)d_in[11];
    const float* be2   = (const float*)d_in[12];
    const float* lne_g = (const float*)d_in[13];
    const float* lne_b = (const float*)d_in[14];
    const float* attnA = (const float*)d_in[15];
    const float* Wo    = (const float*)d_in[16];
    const float* bo    = (const float*)d_in[17];
    const float* lno_g = (const float*)d_in[18];
    const float* lno_b = (const float*)d_in[19];

    float* out     = (float*)d_out;
    float* e_out   = out + (size_t)ROWS * FF;
    float* adj_out = e_out + (size_t)NPOS * EE;

    k_node<<<ROWS/64, 256>>>(node, ln1_g, ln1_b, Wn, bn, attnA);
    k_edge<<<NPOS/256, 128>>>(edge, ln2_g, ln2_b, We1, be1, We2, be2,
                              lne_g, lne_b, attnA, e_out);
    k_attn<<<dim3(NN/16, BB), 256>>>(adj);
    k_out<<<ROWS/64, 256>>>(node, Wo, bo, lno_g, lno_b, out);
    k_adj<<<NPOS/1024, 256>>>(adj, adj_out);
}